// round 13
// baseline (speedup 1.0000x reference)
#include <cuda_runtime.h>
#include <cuda_bf16.h>

// Problem constants
#define NB        512   // batch
#define NCQ       512   // cliques
#define KQ        4     // vars per clique
#define SQ        8     // states
#define HH        128   // hidden
#define BT        64    // batch rows per CTA tile
#define ROWS      256   // BT*KQ rows of h1 per CTA
#define NTHREADS  256
#define WSTR      68    // u32 row stride for bf16 matrices (136 bf16 = conflict-free pad)
#define SMEM_BYTES 143520

static __device__ __forceinline__ void mma16816(float c[4], const unsigned a[4],
                                                unsigned b0, unsigned b1v) {
    asm volatile(
        "mma.sync.aligned.m16n8k16.row.col.f32.bf16.bf16.f32 "
        "{%0,%1,%2,%3}, {%4,%5,%6,%7}, {%8,%9}, {%0,%1,%2,%3};\n"
        : "+f"(c[0]), "+f"(c[1]), "+f"(c[2]), "+f"(c[3])
        : "r"(a[0]), "r"(a[1]), "r"(a[2]), "r"(a[3]), "r"(b0), "r"(b1v));
}

__global__ void __launch_bounds__(NTHREADS, 1)
jt_kernel(const int* __restrict__ x, const float* __restrict__ W1,
          const float* __restrict__ b1, const float* __restrict__ W2,
          const float* __restrict__ b2, const float* __restrict__ W3,
          const float* __restrict__ b3, float* __restrict__ out)
{
    const int n    = blockIdx.y;      // clique
    const int tile = blockIdx.x;      // batch tile
    const int tid  = threadIdx.x;
    const int wid  = tid >> 5;
    const int lane = tid & 31;
    const int g    = lane >> 2;       // mma groupID
    const int t    = lane & 3;        // mma threadID-in-group

    extern __shared__ char sm_raw[];
    float*    sW1  = (float*)sm_raw;                      // [64][128] f32   32768 B
    unsigned* sW2T = (unsigned*)(sm_raw + 32768);         // [128][68] u32   34816 B (bf16 W2^T, padded)
    unsigned* sH1  = (unsigned*)(sm_raw + 67584);         // [256][68] u32   69632 B (bf16 h1, padded)
    float*    sb1  = (float*)(sm_raw + 137216);           // 128 f32
    float*    sb2  = sb1 + HH;                            // 128 f32
    float*    sb3  = sb2 + HH;                            // 8 f32
    unsigned* sW3T = (unsigned*)(sb3 + 8);                // [8][68] u32 (bf16 W3^T)
    int*      sxo  = (int*)(sW3T + 8 * WSTR);             // 256 own states  [b*4+j]
    int*      sxp  = sxo + ROWS;                          // 256 parent states
    float*    slp  = (float*)(sxp + ROWS);                // 256 logp_obs

    // ---------------- stage weights / states into smem ----------------
    {   // W1 (fp32, exact) — coalesced float4 copy
        const float4* g4 = (const float4*)(W1 + (size_t)n * 64 * HH);
        float4* s4 = (float4*)sW1;
        #pragma unroll
        for (int i = tid; i < 64 * HH / 4; i += NTHREADS) s4[i] = g4[i];
    }
    if (tid < HH) { sb1[tid] = b1[n * HH + tid]; sb2[tid] = b2[n * HH + tid]; }
    if (tid < 8)  sb3[tid] = b3[n * 8 + tid];
    {   // W2^T bf16: sW2T[h_out][h_in pair]; gmem reads coalesced over h_out
        const float* gW2 = W2 + (size_t)n * HH * HH;
        for (int e = tid; e < 8192; e += NTHREADS) {
            int o = e & 127, ip = e >> 7;
            __nv_bfloat162 p = __floats2bfloat162_rn(gW2[(2 * ip) * HH + o],
                                                     gW2[(2 * ip + 1) * HH + o]);
            sW2T[o * WSTR + ip] = *(unsigned*)&p;
        }
    }
    {   // W3^T bf16: sW3T[s][h pair]
        const float* gW3 = W3 + (size_t)n * HH * SQ;
        for (int e = tid; e < 512; e += NTHREADS) {
            int s = e >> 6, ip = e & 63;
            __nv_bfloat162 p = __floats2bfloat162_rn(gW3[(2 * ip) * SQ + s],
                                                     gW3[(2 * ip + 1) * SQ + s]);
            sW3T[s * WSTR + ip] = *(unsigned*)&p;
        }
    }
    {   // clique states (own + parent) for the 64 batch rows of this tile
        int bl = tid >> 2, j = tid & 3;
        const int* xr = x + (size_t)(tile * BT + bl) * (NCQ * KQ);
        sxo[tid] = xr[n * KQ + j];
        sxp[tid] = (n > 0) ? xr[(n - 1) * KQ + j] : 0;
    }
    __syncthreads();

    // ---------------- layer 1: sparse one-hot gather (fp32 exact) ----------------
    // warp w owns batch rows b_local in [8w, 8w+8)  =>  h1 rows [32w, 32w+32)
    {
        const int l = lane;
        #pragma unroll
        for (int bi = 0; bi < 8; bi++) {
            int bl = wid * 8 + bi;
            float4 acc = ((const float4*)sb1)[l];
            if (n > 0) {
                #pragma unroll
                for (int j = 0; j < 4; j++) {
                    int row = j * SQ + sxp[bl * 4 + j];
                    float4 v = ((const float4*)(sW1 + row * HH))[l];
                    acc.x += v.x; acc.y += v.y; acc.z += v.z; acc.w += v.w;
                }
            }
            int r0 = bl * 4;
            #pragma unroll
            for (int k = 0; k < 4; k++) {
                if (k > 0) {    // incremental autoregressive prefix
                    int row = 32 + (k - 1) * SQ + sxo[bl * 4 + (k - 1)];
                    float4 v = ((const float4*)(sW1 + row * HH))[l];
                    acc.x += v.x; acc.y += v.y; acc.z += v.z; acc.w += v.w;
                }
                __nv_bfloat162 p0 = __floats2bfloat162_rn(fmaxf(acc.x, 0.f), fmaxf(acc.y, 0.f));
                __nv_bfloat162 p1 = __floats2bfloat162_rn(fmaxf(acc.z, 0.f), fmaxf(acc.w, 0.f));
                unsigned* dst = sH1 + (r0 + k) * WSTR + 2 * l;
                dst[0] = *(unsigned*)&p0;
                dst[1] = *(unsigned*)&p1;
            }
        }
    }
    __syncwarp();   // each warp only reads its own 32 rows below

    // ---------------- layer 2: h2 = relu(h1 @ W2 + b2), bf16 HMMA, f32 accum ----------------
    // pA: layer-3 A fragments built directly from layer-2 C fragments.
    unsigned pA[2][32];
    #pragma unroll
    for (int nh = 0; nh < 2; nh++) {               // N halves (cols 0-63, 64-127)
        float c[2][8][4];
        #pragma unroll
        for (int mt = 0; mt < 2; mt++)
            #pragma unroll
            for (int nb = 0; nb < 8; nb++)
                #pragma unroll
                for (int q = 0; q < 4; q++) c[mt][nb][q] = 0.f;

        #pragma unroll
        for (int kk = 0; kk < 8; kk++) {           // k-steps of 16
            unsigned a[2][4];
            #pragma unroll
            for (int mt = 0; mt < 2; mt++) {
                int rb = wid * 32 + mt * 16;
                const unsigned* p0 = sH1 + (rb + g) * WSTR + kk * 8 + t;
                const unsigned* p1 = sH1 + (rb + 8 + g) * WSTR + kk * 8 + t;
                a[mt][0] = p0[0]; a[mt][2] = p0[4];
                a[mt][1] = p1[0]; a[mt][3] = p1[4];
            }
            #pragma unroll
            for (int nb = 0; nb < 8; nb++) {
                int ncol = nh * 64 + nb * 8 + g;
                unsigned b0v = sW2T[ncol * WSTR + kk * 8 + t];
                unsigned b1v = sW2T[ncol * WSTR + kk * 8 + 4 + t];
                mma16816(c[0][nb], a[0], b0v, b1v);
                mma16816(c[1][nb], a[1], b0v, b1v);
            }
        }
        // epilogue: + b2, relu, pack to bf16 layer-3 A fragments (no smem round trip)
        #pragma unroll
        for (int nb = 0; nb < 8; nb++) {
            int col0 = nh * 64 + nb * 8 + 2 * t;
            float bb0 = sb2[col0], bb1 = sb2[col0 + 1];
            int nbg = nh * 8 + nb;
            #pragma unroll
            for (int mt = 0; mt < 2; mt++) {
                float r0 = fmaxf(c[mt][nb][0] + bb0, 0.f);
                float r1 = fmaxf(c[mt][nb][1] + bb1, 0.f);
                float r2 = fmaxf(c[mt][nb][2] + bb0, 0.f);
                float r3 = fmaxf(c[mt][nb][3] + bb1, 0.f);
                __nv_bfloat162 q0 = __floats2bfloat162_rn(r0, r1);
                __nv_bfloat162 q1 = __floats2bfloat162_rn(r2, r3);
                pA[mt][nbg * 2]     = *(unsigned*)&q0;   // rows g
                pA[mt][nbg * 2 + 1] = *(unsigned*)&q1;   // rows g+8
            }
        }
    }

    // ---------------- layer 3: logits = h2 @ W3 + b3 (mma from register fragments) ----------------
    float d[2][4] = {{0.f,0.f,0.f,0.f},{0.f,0.f,0.f,0.f}};
    #pragma unroll
    for (int kk = 0; kk < 8; kk++) {
        unsigned b0v = sW3T[g * WSTR + kk * 8 + t];
        unsigned b1v = sW3T[g * WSTR + kk * 8 + 4 + t];
        #pragma unroll
        for (int mt = 0; mt < 2; mt++) {
            const unsigned a[4] = { pA[mt][4 * kk], pA[mt][4 * kk + 1],
                                    pA[mt][4 * kk + 2], pA[mt][4 * kk + 3] };
            mma16816(d[mt], a, b0v, b1v);
        }
    }

    // ---------------- log-softmax over S=8 (4-lane quad reduce) + observed gather ----------------
    {
        float bb0 = sb3[2 * t], bb1 = sb3[2 * t + 1];
        #pragma unroll
        for (int mt = 0; mt < 2; mt++) {
            #pragma unroll
            for (int h = 0; h < 2; h++) {           // row g (h=0) / row g+8 (h=1)
                float l0 = d[mt][2 * h]     + bb0;  // state 2t
                float l1 = d[mt][2 * h + 1] + bb1;  // state 2t+1
                float mx = fmaxf(l0, l1);
                mx = fmaxf(mx, __shfl_xor_sync(0xffffffffu, mx, 1));
                mx = fmaxf(mx, __shfl_xor_sync(0xffffffffu, mx, 2));
                float sum = __expf(l0 - mx) + __expf(l1 - mx);
                sum += __shfl_xor_sync(0xffffffffu, sum, 1);
                sum += __shfl_xor_sync(0xffffffffu, sum, 2);
                float lse = mx + __logf(sum);
                int row = wid * 32 + mt * 16 + h * 8 + g;   // == b_local*4 + k
                int sobs = sxo[row];
                if ((sobs >> 1) == t)
                    slp[row] = ((sobs & 1) ? l1 : l0) - lse;
            }
        }
    }
    __syncthreads();

    // ---------------- sum over K positions, write out[b, n] ----------------
    if (tid < BT) {
        float s = slp[4 * tid] + slp[4 * tid + 1] + slp[4 * tid + 2] + slp[4 * tid + 3];
        out[(size_t)(tile * BT + tid) * NCQ + n] = s;
    }
}

extern "C" void kernel_launch(void* const* d_in, const int* in_sizes, int n_in,
                              void* d_out, int out_size) {
    (void)in_sizes; (void)n_in; (void)out_size;
    cudaFuncSetAttribute(jt_kernel, cudaFuncAttributeMaxDynamicSharedMemorySize, SMEM_BYTES);
    dim3 grid(NB / BT, NCQ);   // x = batch tile (fast) -> same-clique CTAs adjacent for L2 reuse
    jt_kernel<<<grid, NTHREADS, SMEM_BYTES>>>(
        (const int*)d_in[0], (const float*)d_in[1], (const float*)d_in[2],
        (const float*)d_in[3], (const float*)d_in[4], (const float*)d_in[5],
        (const float*)d_in[6], (float*)d_out);
}

// round 14
// speedup vs baseline: 1.0095x; 1.0095x over previous
#include <cuda_runtime.h>
#include <cuda_bf16.h>

// Problem constants
#define NB        512   // batch
#define NCQ       512   // cliques
#define KQ        4     // vars per clique
#define SQ        8     // states
#define HH        128   // hidden
#define BT        64    // batch rows per CTA tile
#define ROWS      256   // BT*KQ rows of h1 per CTA
#define NTHREADS  256
#define WSTR      68    // u32 row stride for bf16 matrices (136 bf16 = conflict-free pad)

// smem layout sizes (bytes)
#define OFF_W2T   0
#define OFF_H1    34816                     // after W2T (128*68*4)
#define OFF_MISC  (34816 + 69632)           // after H1 (256*68*4)
#define SMEM_BYTES (OFF_MISC + 512 + 512 + 32 + 2176 + 1024 + 1024 + 1024)  // 110752

static __device__ __forceinline__ void mma16816(float c[4], const unsigned a[4],
                                                unsigned b0, unsigned b1v) {
    asm volatile(
        "mma.sync.aligned.m16n8k16.row.col.f32.bf16.bf16.f32 "
        "{%0,%1,%2,%3}, {%4,%5,%6,%7}, {%8,%9}, {%0,%1,%2,%3};\n"
        : "+f"(c[0]), "+f"(c[1]), "+f"(c[2]), "+f"(c[3])
        : "r"(a[0]), "r"(a[1]), "r"(a[2]), "r"(a[3]), "r"(b0), "r"(b1v));
}

__global__ void __launch_bounds__(NTHREADS, 2)
jt_kernel(const int* __restrict__ x, const float* __restrict__ W1,
          const float* __restrict__ b1, const float* __restrict__ W2,
          const float* __restrict__ b2, const float* __restrict__ W3,
          const float* __restrict__ b3, float* __restrict__ out)
{
    const int n    = blockIdx.y;      // clique
    const int tile = blockIdx.x;      // batch tile
    const int tid  = threadIdx.x;
    const int wid  = tid >> 5;
    const int lane = tid & 31;
    const int g    = lane >> 2;       // mma groupID
    const int t    = lane & 3;        // mma threadID-in-group

    extern __shared__ char sm_raw[];
    unsigned* sW2T = (unsigned*)(sm_raw + OFF_W2T);       // [128][68] u32 (bf16 W2^T, padded)
    unsigned* sH1  = (unsigned*)(sm_raw + OFF_H1);        // [256][68] u32 (bf16 h1, padded)
    float*    sb1  = (float*)(sm_raw + OFF_MISC);         // 128 f32
    float*    sb2  = sb1 + HH;                            // 128 f32
    float*    sb3  = sb2 + HH;                            // 8 f32
    unsigned* sW3T = (unsigned*)(sb3 + 8);                // [8][68] u32 (bf16 W3^T)
    int*      sxo  = (int*)(sW3T + 8 * WSTR);             // 256 own states  [b*4+j]
    int*      sxp  = sxo + ROWS;                          // 256 parent states
    float*    slp  = (float*)(sxp + ROWS);                // 256 logp_obs

    // ---------------- stage weights / states into smem ----------------
    if (tid < HH) { sb1[tid] = b1[n * HH + tid]; sb2[tid] = b2[n * HH + tid]; }
    if (tid < 8)  sb3[tid] = b3[n * 8 + tid];
    {   // W2^T bf16: sW2T[h_out][h_in pair]; gmem reads coalesced over h_out
        const float* gW2 = W2 + (size_t)n * HH * HH;
        for (int e = tid; e < 8192; e += NTHREADS) {
            int o = e & 127, ip = e >> 7;
            __nv_bfloat162 p = __floats2bfloat162_rn(gW2[(2 * ip) * HH + o],
                                                     gW2[(2 * ip + 1) * HH + o]);
            sW2T[o * WSTR + ip] = *(unsigned*)&p;
        }
    }
    {   // W3^T bf16: sW3T[s][h pair]
        const float* gW3 = W3 + (size_t)n * HH * SQ;
        for (int e = tid; e < 512; e += NTHREADS) {
            int s = e >> 6, ip = e & 63;
            __nv_bfloat162 p = __floats2bfloat162_rn(gW3[(2 * ip) * SQ + s],
                                                     gW3[(2 * ip + 1) * SQ + s]);
            sW3T[s * WSTR + ip] = *(unsigned*)&p;
        }
    }
    {   // clique states (own + parent) for the 64 batch rows of this tile
        int bl = tid >> 2, j = tid & 3;
        const int* xr = x + (size_t)(tile * BT + bl) * (NCQ * KQ);
        sxo[tid] = xr[n * KQ + j];
        sxp[tid] = (n > 0) ? xr[(n - 1) * KQ + j] : 0;
    }
    __syncthreads();

    // ---------------- layer 1: sparse one-hot gather (fp32 exact, W1 rows from L2) ----------------
    // warp w owns batch rows b_local in [8w, 8w+8)  =>  h1 rows [32w, 32w+32)
    {
        const float* gW1 = W1 + (size_t)n * 64 * HH;
        const int l = lane;
        #pragma unroll
        for (int bi = 0; bi < 8; bi++) {
            int bl = wid * 8 + bi;
            float4 acc = ((const float4*)sb1)[l];
            if (n > 0) {
                #pragma unroll
                for (int j = 0; j < 4; j++) {
                    int row = j * SQ + sxp[bl * 4 + j];
                    float4 v = __ldg((const float4*)(gW1 + row * HH) + l);
                    acc.x += v.x; acc.y += v.y; acc.z += v.z; acc.w += v.w;
                }
            }
            int r0 = bl * 4;
            #pragma unroll
            for (int k = 0; k < 4; k++) {
                if (k > 0) {    // incremental autoregressive prefix
                    int row = 32 + (k - 1) * SQ + sxo[bl * 4 + (k - 1)];
                    float4 v = __ldg((const float4*)(gW1 + row * HH) + l);
                    acc.x += v.x; acc.y += v.y; acc.z += v.z; acc.w += v.w;
                }
                __nv_bfloat162 p0 = __floats2bfloat162_rn(fmaxf(acc.x, 0.f), fmaxf(acc.y, 0.f));
                __nv_bfloat162 p1 = __floats2bfloat162_rn(fmaxf(acc.z, 0.f), fmaxf(acc.w, 0.f));
                unsigned* dst = sH1 + (r0 + k) * WSTR + 2 * l;
                dst[0] = *(unsigned*)&p0;
                dst[1] = *(unsigned*)&p1;
            }
        }
    }
    __syncwarp();   // each warp only reads its own 32 rows below

    // ---------------- layers 2+3 in two 16-row (mt) passes to cap registers ----------------
    #pragma unroll
    for (int mt = 0; mt < 2; mt++) {
        const int rb = wid * 32 + mt * 16;
        float d[4] = {0.f, 0.f, 0.f, 0.f};           // layer-3 logits accumulator

        #pragma unroll
        for (int nh = 0; nh < 2; nh++) {             // layer-2 N halves (cols 0-63 / 64-127)
            float c[8][4];
            #pragma unroll
            for (int nb = 0; nb < 8; nb++)
                #pragma unroll
                for (int q = 0; q < 4; q++) c[nb][q] = 0.f;

            #pragma unroll
            for (int kk = 0; kk < 8; kk++) {         // k-steps of 16
                unsigned a[4];
                const unsigned* p0 = sH1 + (rb + g) * WSTR + kk * 8 + t;
                const unsigned* p1 = sH1 + (rb + 8 + g) * WSTR + kk * 8 + t;
                a[0] = p0[0]; a[2] = p0[4];
                a[1] = p1[0]; a[3] = p1[4];
                #pragma unroll
                for (int nb = 0; nb < 8; nb++) {
                    int ncol = nh * 64 + nb * 8 + g;
                    unsigned b0v = sW2T[ncol * WSTR + kk * 8 + t];
                    unsigned b1v = sW2T[ncol * WSTR + kk * 8 + 4 + t];
                    mma16816(c[nb], a, b0v, b1v);
                }
            }

            // epilogue: + b2, relu, pack to bf16 layer-3 A fragments (registers only)
            unsigned pA[16];
            #pragma unroll
            for (int nb = 0; nb < 8; nb++) {
                int col0 = nh * 64 + nb * 8 + 2 * t;
                float bb0 = sb2[col0], bb1 = sb2[col0 + 1];
                float r0 = fmaxf(c[nb][0] + bb0, 0.f);
                float r1 = fmaxf(c[nb][1] + bb1, 0.f);
                float r2 = fmaxf(c[nb][2] + bb0, 0.f);
                float r3 = fmaxf(c[nb][3] + bb1, 0.f);
                __nv_bfloat162 q0 = __floats2bfloat162_rn(r0, r1);
                __nv_bfloat162 q1 = __floats2bfloat162_rn(r2, r3);
                pA[2 * nb]     = *(unsigned*)&q0;    // rows g
                pA[2 * nb + 1] = *(unsigned*)&q1;    // rows g+8
            }

            // layer-3 partial accumulation over this half's 4 k-tiles
            #pragma unroll
            for (int kk2 = 0; kk2 < 4; kk2++) {
                int kkt = nh * 4 + kk2;
                unsigned b0v = sW3T[g * WSTR + kkt * 8 + t];
                unsigned b1v = sW3T[g * WSTR + kkt * 8 + 4 + t];
                const unsigned a[4] = { pA[4 * kk2], pA[4 * kk2 + 1],
                                        pA[4 * kk2 + 2], pA[4 * kk2 + 3] };
                mma16816(d, a, b0v, b1v);
            }
        }

        // ---- log-softmax over S=8 (quad reduce) + observed-state gather for these 16 rows ----
        float bb0 = sb3[2 * t], bb1 = sb3[2 * t + 1];
        #pragma unroll
        for (int h = 0; h < 2; h++) {                // row g (h=0) / row g+8 (h=1)
            float l0 = d[2 * h]     + bb0;           // state 2t
            float l1 = d[2 * h + 1] + bb1;           // state 2t+1
            float mx = fmaxf(l0, l1);
            mx = fmaxf(mx, __shfl_xor_sync(0xffffffffu, mx, 1));
            mx = fmaxf(mx, __shfl_xor_sync(0xffffffffu, mx, 2));
            float sum = __expf(l0 - mx) + __expf(l1 - mx);
            sum += __shfl_xor_sync(0xffffffffu, sum, 1);
            sum += __shfl_xor_sync(0xffffffffu, sum, 2);
            float lse = mx + __logf(sum);
            int row = rb + h * 8 + g;                // == b_local*4 + k
            int sobs = sxo[row];
            if ((sobs >> 1) == t)
                slp[row] = ((sobs & 1) ? l1 : l0) - lse;
        }
    }
    __syncthreads();

    // ---------------- sum over K positions, write out[b, n] ----------------
    if (tid < BT) {
        float s = slp[4 * tid] + slp[4 * tid + 1] + slp[4 * tid + 2] + slp[4 * tid + 3];
        out[(size_t)(tile * BT + tid) * NCQ + n] = s;
    }
}

extern "C" void kernel_launch(void* const* d_in, const int* in_sizes, int n_in,
                              void* d_out, int out_size) {
    (void)in_sizes; (void)n_in; (void)out_size;
    cudaFuncSetAttribute(jt_kernel, cudaFuncAttributeMaxDynamicSharedMemorySize, SMEM_BYTES);
    dim3 grid(NB / BT, NCQ);   // x = batch tile (fast) -> same-clique CTAs adjacent for L2 reuse
    jt_kernel<<<grid, NTHREADS, SMEM_BYTES>>>(
        (const int*)d_in[0], (const float*)d_in[1], (const float*)d_in[2],
        (const float*)d_in[3], (const float*)d_in[4], (const float*)d_in[5],
        (const float*)d_in[6], (float*)d_out);
}

// round 15
// speedup vs baseline: 1.3489x; 1.3363x over previous
#include <cuda_runtime.h>
#include <cuda_bf16.h>

// Problem constants
#define NB        512   // batch
#define NCQ       512   // cliques
#define KQ        4     // vars per clique
#define SQ        8     // states
#define HH        128   // hidden
#define BT        64    // batch rows per CTA tile
#define ROWS      256   // BT*KQ rows of h1 per CTA
#define NTHREADS  256
#define H1STR     68    // u32 row stride for sH1 (conflict-free LDS.32: 68 % 32 == 4)
#define W2STR     72    // u32 row stride for sW2T/sW3T (conflict-free LDS.64: 36 8B-banks % 16 == 4)

// smem layout (bytes)
#define OFF_W2T   0                         // 128*72*4 = 36864
#define OFF_H1    36864                     // 128*68*4 = 34816 (8 warps x 16-row chunk)
#define OFF_B1    71680                     // 512
#define OFF_B2    72192                     // 512
#define OFF_B3    72704                     // 32
#define OFF_W3T   72736                     // 8*72*4 = 2304
#define OFF_XO    75040                     // 256 (char)
#define OFF_XP    75296                     // 256 (char)
#define OFF_LP    75552                     // 1024
#define SMEM_BYTES 76576

static __device__ __forceinline__ void mma16816(float c[4], const unsigned a[4],
                                                unsigned b0, unsigned b1v) {
    asm volatile(
        "mma.sync.aligned.m16n8k16.row.col.f32.bf16.bf16.f32 "
        "{%0,%1,%2,%3}, {%4,%5,%6,%7}, {%8,%9}, {%0,%1,%2,%3};\n"
        : "+f"(c[0]), "+f"(c[1]), "+f"(c[2]), "+f"(c[3])
        : "r"(a[0]), "r"(a[1]), "r"(a[2]), "r"(a[3]), "r"(b0), "r"(b1v));
}

__global__ void __launch_bounds__(NTHREADS, 3)
jt_kernel(const int* __restrict__ x, const float* __restrict__ W1,
          const float* __restrict__ b1, const float* __restrict__ W2,
          const float* __restrict__ b2, const float* __restrict__ W3,
          const float* __restrict__ b3, float* __restrict__ out)
{
    const int n    = blockIdx.y;      // clique
    const int tile = blockIdx.x;      // batch tile
    const int tid  = threadIdx.x;
    const int wid  = tid >> 5;
    const int lane = tid & 31;
    const int g    = lane >> 2;       // mma groupID
    const int t    = lane & 3;        // mma threadID-in-group

    extern __shared__ char sm_raw[];
    unsigned* sW2T = (unsigned*)(sm_raw + OFF_W2T);  // [128 rows][72] (bf16x2 pairs, LDS.64 layout)
    unsigned* sH1  = (unsigned*)(sm_raw + OFF_H1);   // [8 warps][16 rows][68]
    float*    sb1  = (float*)(sm_raw + OFF_B1);
    float*    sb2  = (float*)(sm_raw + OFF_B2);
    float*    sb3  = (float*)(sm_raw + OFF_B3);
    unsigned* sW3T = (unsigned*)(sm_raw + OFF_W3T);  // [8 rows][72]
    char*     sxo  = (char*)(sm_raw + OFF_XO);       // own states [b*4+j]
    char*     sxp  = (char*)(sm_raw + OFF_XP);       // parent states
    float*    slp  = (float*)(sm_raw + OFF_LP);      // 256 logp_obs

    // ---------------- stage weights / states into smem ----------------
    if (tid < HH) { sb1[tid] = b1[n * HH + tid]; sb2[tid] = b2[n * HH + tid]; }
    if (tid < 8)  sb3[tid] = b3[n * 8 + tid];
    {   // W2^T bf16, paired layout: 8B unit (o, kk, t) at o*72 + kk*8 + 2*(t ^ (o&3) ^ ((o>>2)&3))
        // holds { k-pair (16kk+2t, +1) , k-pair (16kk+8+2t, +1) } for output col o.
        const float* gW2 = W2 + (size_t)n * HH * HH;
        #pragma unroll
        for (int it = 0; it < 16; it++) {
            int u = it * NTHREADS + tid;
            int o = u & 127, s = u >> 7;      // s in 0..31
            int kk = s >> 2, tt = s & 3;
            int ip0 = kk * 8 + tt, ip1 = ip0 + 4;
            __nv_bfloat162 p0 = __floats2bfloat162_rn(gW2[(2 * ip0) * HH + o],
                                                      gW2[(2 * ip0 + 1) * HH + o]);
            __nv_bfloat162 p1 = __floats2bfloat162_rn(gW2[(2 * ip1) * HH + o],
                                                      gW2[(2 * ip1 + 1) * HH + o]);
            int j = tt ^ (o & 3) ^ ((o >> 2) & 3);
            uint2 v; v.x = *(unsigned*)&p0; v.y = *(unsigned*)&p1;
            *(uint2*)(sW2T + o * W2STR + kk * 8 + 2 * j) = v;
        }
    }
    if (tid < 256) {   // W3^T bf16, same paired layout (8 rows)
        const float* gW3 = W3 + (size_t)n * HH * SQ;
        int o = tid & 7, s = tid >> 3;        // s in 0..31
        int kk = s >> 2, tt = s & 3;
        int ip0 = kk * 8 + tt, ip1 = ip0 + 4;
        __nv_bfloat162 p0 = __floats2bfloat162_rn(gW3[(2 * ip0) * SQ + o],
                                                  gW3[(2 * ip0 + 1) * SQ + o]);
        __nv_bfloat162 p1 = __floats2bfloat162_rn(gW3[(2 * ip1) * SQ + o],
                                                  gW3[(2 * ip1 + 1) * SQ + o]);
        int j = tt ^ (o & 3) ^ ((o >> 2) & 3);
        uint2 v; v.x = *(unsigned*)&p0; v.y = *(unsigned*)&p1;
        *(uint2*)(sW3T + o * W2STR + kk * 8 + 2 * j) = v;
    }
    {   // clique states (own + parent), byte-packed
        int bl = tid >> 2, j = tid & 3;
        const int* xr = x + (size_t)(tile * BT + bl) * (NCQ * KQ);
        sxo[tid] = (char)xr[n * KQ + j];
        sxp[tid] = (n > 0) ? (char)xr[(n - 1) * KQ + j] : 0;
    }
    __syncthreads();

    const float* gW1 = W1 + (size_t)n * 64 * HH;
    const int jx = t ^ (g & 3);                         // LDS.64 swizzle base (g>>2 term added per-row)
    const int jx3 = t ^ (g & 3) ^ ((g >> 2) & 3);       // W3T row = g

    // ---------------- two 16-row chunks per warp: layer1 -> layers2+3 ----------------
    #pragma unroll
    for (int c = 0; c < 2; c++) {
        // ---- layer 1: sparse one-hot gather (fp32 exact, W1 rows via L2) ----
        __syncwarp();                                   // chunk buffer reuse ordering
        #pragma unroll
        for (int bi = 0; bi < 4; bi++) {
            int bl = wid * 8 + c * 4 + bi;              // batch row (local)
            float4 acc = ((const float4*)sb1)[lane];
            if (n > 0) {
                #pragma unroll
                for (int j = 0; j < 4; j++) {
                    int row = j * SQ + (int)sxp[bl * 4 + j];
                    float4 v = __ldg((const float4*)(gW1 + row * HH) + lane);
                    acc.x += v.x; acc.y += v.y; acc.z += v.z; acc.w += v.w;
                }
            }
            int r0 = wid * 16 + bi * 4;                 // buffer row base
            #pragma unroll
            for (int k = 0; k < 4; k++) {
                if (k > 0) {                            // incremental autoregressive prefix
                    int row = 32 + (k - 1) * SQ + (int)sxo[bl * 4 + (k - 1)];
                    float4 v = __ldg((const float4*)(gW1 + row * HH) + lane);
                    acc.x += v.x; acc.y += v.y; acc.z += v.z; acc.w += v.w;
                }
                __nv_bfloat162 p0 = __floats2bfloat162_rn(fmaxf(acc.x, 0.f), fmaxf(acc.y, 0.f));
                __nv_bfloat162 p1 = __floats2bfloat162_rn(fmaxf(acc.z, 0.f), fmaxf(acc.w, 0.f));
                unsigned* dst = sH1 + (r0 + k) * H1STR + 2 * lane;
                dst[0] = *(unsigned*)&p0;
                dst[1] = *(unsigned*)&p1;
            }
        }
        __syncwarp();

        // ---- layers 2+3 on this 16-row chunk ----
        float d[4] = {0.f, 0.f, 0.f, 0.f};              // layer-3 logits accumulator

        #pragma unroll
        for (int nh = 0; nh < 2; nh++) {                // layer-2 N halves
            float cc[8][4];
            #pragma unroll
            for (int nb = 0; nb < 8; nb++)
                #pragma unroll
                for (int q = 0; q < 4; q++) cc[nb][q] = 0.f;

            #pragma unroll
            for (int kk = 0; kk < 8; kk++) {            // k-steps of 16
                unsigned a[4];
                const unsigned* p0 = sH1 + (wid * 16 + g) * H1STR + kk * 8 + t;
                a[0] = p0[0]; a[2] = p0[4];
                a[1] = p0[8 * H1STR]; a[3] = p0[8 * H1STR + 4];
                #pragma unroll
                for (int nb = 0; nb < 8; nb++) {
                    int ncol = nh * 64 + nb * 8 + g;
                    int j = jx ^ ((2 * nb + (g >> 2)) & 3);
                    uint2 bq = *(const uint2*)(sW2T + ncol * W2STR + kk * 8 + 2 * j);
                    mma16816(cc[nb], a, bq.x, bq.y);
                }
            }

            // epilogue: + b2, relu, pack to bf16 layer-3 A fragments (registers only)
            unsigned pA[16];
            #pragma unroll
            for (int nb = 0; nb < 8; nb++) {
                int col0 = nh * 64 + nb * 8 + 2 * t;
                float bb0 = sb2[col0], bb1 = sb2[col0 + 1];
                float r0 = fmaxf(cc[nb][0] + bb0, 0.f);
                float r1 = fmaxf(cc[nb][1] + bb1, 0.f);
                float r2 = fmaxf(cc[nb][2] + bb0, 0.f);
                float r3 = fmaxf(cc[nb][3] + bb1, 0.f);
                __nv_bfloat162 q0 = __floats2bfloat162_rn(r0, r1);
                __nv_bfloat162 q1 = __floats2bfloat162_rn(r2, r3);
                pA[2 * nb]     = *(unsigned*)&q0;       // rows g
                pA[2 * nb + 1] = *(unsigned*)&q1;       // rows g+8
            }

            // layer-3 partial accumulation over this half's 4 k-tiles
            #pragma unroll
            for (int kk2 = 0; kk2 < 4; kk2++) {
                int kkt = nh * 4 + kk2;
                uint2 bq = *(const uint2*)(sW3T + g * W2STR + kkt * 8 + 2 * jx3);
                const unsigned a[4] = { pA[4 * kk2], pA[4 * kk2 + 1],
                                        pA[4 * kk2 + 2], pA[4 * kk2 + 3] };
                mma16816(d, a, bq.x, bq.y);
            }
        }

        // ---- log-softmax over S=8 (quad reduce) + observed-state gather ----
        float bb0 = sb3[2 * t], bb1 = sb3[2 * t + 1];
        #pragma unroll
        for (int h = 0; h < 2; h++) {                   // row g (h=0) / row g+8 (h=1)
            float l0 = d[2 * h]     + bb0;              // state 2t
            float l1 = d[2 * h + 1] + bb1;              // state 2t+1
            float mx = fmaxf(l0, l1);
            mx = fmaxf(mx, __shfl_xor_sync(0xffffffffu, mx, 1));
            mx = fmaxf(mx, __shfl_xor_sync(0xffffffffu, mx, 2));
            float sum = __expf(l0 - mx) + __expf(l1 - mx);
            sum += __shfl_xor_sync(0xffffffffu, sum, 1);
            sum += __shfl_xor_sync(0xffffffffu, sum, 2);
            float lse = mx + __logf(sum);
            int row = wid * 32 + c * 16 + h * 8 + g;    // global (b_local*4 + k)
            int sobs = (int)sxo[row];
            if ((sobs >> 1) == t)
                slp[row] = ((sobs & 1) ? l1 : l0) - lse;
        }
    }
    __syncthreads();

    // ---------------- sum over K positions, write out[b, n] ----------------
    if (tid < BT) {
        float s = slp[4 * tid] + slp[4 * tid + 1] + slp[4 * tid + 2] + slp[4 * tid + 3];
        out[(size_t)(tile * BT + tid) * NCQ + n] = s;
    }
}

extern "C" void kernel_launch(void* const* d_in, const int* in_sizes, int n_in,
                              void* d_out, int out_size) {
    (void)in_sizes; (void)n_in; (void)out_size;
    cudaFuncSetAttribute(jt_kernel, cudaFuncAttributeMaxDynamicSharedMemorySize, SMEM_BYTES);
    dim3 grid(NB / BT, NCQ);   // x = batch tile (fast) -> same-clique CTAs adjacent for L2 reuse
    jt_kernel<<<grid, NTHREADS, SMEM_BYTES>>>(
        (const int*)d_in[0], (const float*)d_in[1], (const float*)d_in[2],
        (const float*)d_in[3], (const float*)d_in[4], (const float*)d_in[5],
        (const float*)d_in[6], (float*)d_out);
}